// round 16
// baseline (speedup 1.0000x reference)
#include <cuda_runtime.h>
#include <cuda_fp16.h>
#include <cstdint>

#define N_NODES 100000
#define N_PAD   100096
#define E_MAX   700000
#define IN_CH   1280
#define G_CH    128
#define HID     512
#define NCLS    79
#define KCAT    (IN_CH + G_CH)
#define SCAN_B  512

// ---------------- scratch (device globals; no allocation allowed) ----------------
__device__ float  g_dinv[N_NODES];
__device__ int    g_cnt [N_NODES];
__device__ int    g_offs[N_NODES + 1];
__device__ int    g_cur [N_NODES];
__device__ int    g_bsum[256];
__device__ int    g_esrc[E_MAX];
__device__ int    g_i64mode;
__device__ __half g_xwf[(size_t)N_PAD * G_CH];
__device__ __half g_xf [(size_t)N_PAD * IN_CH];
__device__ __half g_x1f[(size_t)N_PAD * G_CH];
__device__ __half g_wgf[G_CH * IN_CH];
__device__ __half g_whf[HID * KCAT];
__device__ __half g_wcf[128 * HID];

// ---------------- PTX helpers ----------------
__device__ __forceinline__ uint32_t smem_u32(const void* p) {
    uint32_t a;
    asm("{ .reg .u64 t; cvta.to.shared.u64 t, %1; cvt.u32.u64 %0, t; }" : "=r"(a) : "l"(p));
    return a;
}
__device__ __forceinline__ void cp16(uint32_t dst, const void* src) {
    asm volatile("cp.async.cg.shared.global [%0], [%1], 16;" :: "r"(dst), "l"(src));
}
__device__ __forceinline__ void ldm_x4(uint32_t* r, uint32_t addr) {
    asm volatile("ldmatrix.sync.aligned.m8n8.x4.shared.b16 {%0,%1,%2,%3}, [%4];"
        : "=r"(r[0]), "=r"(r[1]), "=r"(r[2]), "=r"(r[3]) : "r"(addr));
}
__device__ __forceinline__ void mma16816(float* c, const uint32_t* a, const uint32_t* b) {
    asm volatile("mma.sync.aligned.m16n8k16.row.col.f32.f16.f16.f32 "
        "{%0,%1,%2,%3}, {%4,%5,%6,%7}, {%8,%9}, {%0,%1,%2,%3};"
        : "+f"(c[0]), "+f"(c[1]), "+f"(c[2]), "+f"(c[3])
        : "r"(a[0]), "r"(a[1]), "r"(a[2]), "r"(a[3]), "r"(b[0]), "r"(b[1]));
}
__device__ __forceinline__ void sts16(uint32_t addr, uint32_t a, uint32_t b, uint32_t c, uint32_t d) {
    asm volatile("st.shared.v4.b32 [%0], {%1,%2,%3,%4};" :: "r"(addr), "r"(a), "r"(b), "r"(c), "r"(d));
}
__device__ __forceinline__ uint32_t pack2(float a, float b) {
    __half2 h = __floats2half2_rn(a, b);
    return *reinterpret_cast<uint32_t*>(&h);
}

// ---------------- combined prep: convert all weights + zero g_cnt ----------------
#define WG_TOT (G_CH * IN_CH)
#define WH_TOT (HID * KCAT)
#define WC_TOT (128 * HID)
__global__ void k_prep(const float* __restrict__ Wg, const float* __restrict__ Wh,
                       const float* __restrict__ Wc, int n) {
    int idx = blockIdx.x * blockDim.x + threadIdx.x;
    if (idx < WG_TOT) {
        int nn = idx / IN_CH, k = idx % IN_CH;
        g_wgf[idx] = __float2half_rn(__ldg(&Wg[(size_t)k * G_CH + nn]));
        return;
    }
    idx -= WG_TOT;
    if (idx < WH_TOT) {
        int nn = idx / KCAT, k = idx % KCAT;
        g_whf[idx] = __float2half_rn(__ldg(&Wh[(size_t)k * HID + nn]));
        return;
    }
    idx -= WH_TOT;
    if (idx < WC_TOT) {
        int nn = idx / HID, k = idx % HID;
        float v = (nn < NCLS) ? __ldg(&Wc[(size_t)k * NCLS + nn]) : 0.0f;
        g_wcf[idx] = __float2half_rn(v);
        return;
    }
    idx -= WC_TOT;
    if (idx < n) g_cnt[idx] = 0;
}

// ---------------- pipelined fp16 tensor-core GEMM ----------------
// AFUSE: A read as fp32 (stride K), converted in regs; MIRROR: also store fp16 A
//        to g_xf. Otherwise A via cp.async from fp16 planes with NST-stage pipeline.
// BK: 32 (AFUSE) or 64. NST: 2 or 3 pipeline stages (non-AFUSE only).
template<bool AFUSE, bool MIRROR, int BK, int NST, int AM, int BMODE,
         bool BIAS, bool RELU, bool HOUT, int CM>
__global__ void __launch_bounds__(256, 2)
tc_gemm(const float* __restrict__ Afp32, const float* __restrict__ bias,
        float* __restrict__ Cp, int M, int Nout)
{
    constexpr int RS    = BK + 8;
    constexpr int PLANE = 128 * RS * 2;
    constexpr int STAGE = 2 * PLANE;
    constexpr int GRP   = BK / 8;
    constexpr int IT    = BK / 16;

    extern __shared__ __align__(16) char dsm[];
    const uint32_t base = smem_u32(dsm);

    const int tid  = threadIdx.x;
    const int wid  = tid >> 5;
    const int lane = tid & 31;
    const int wm = wid >> 2;
    const int wn = wid & 3;
    const int m0 = (HOUT ? blockIdx.y : blockIdx.x) * 128;
    const int n0 = (HOUT ? blockIdx.x : blockIdx.y) * 128;

    float acc[4][4][4];
#pragma unroll
    for (int i = 0; i < 4; i++)
#pragma unroll
        for (int j = 0; j < 4; j++)
#pragma unroll
            for (int r = 0; r < 4; r++) acc[i][j][r] = 0.0f;

    constexpr int K  = (AM == 0) ? IN_CH : (AM == 1) ? KCAT : HID;
    constexpr int Kb = (BMODE == 0) ? IN_CH : (BMODE == 1) ? KCAT : HID;
    constexpr int nchunks = K / BK;

    const int lrow = lane & 15;
    const int lko  = (lane >> 4) << 3;

    auto issueB = [&](int ch, int stg) {
        const int k0 = ch * BK;
        const __half* pB = (BMODE == 0) ? g_wgf : (BMODE == 1) ? g_whf : g_wcf;
        const uint32_t sb = base + stg * STAGE + PLANE;
#pragma unroll
        for (int it = 0; it < IT; it++) {
            int o = tid + it * 256;
            int row = o / GRP, grp = o % GRP;
            cp16(sb + (uint32_t)(row * (RS * 2) + grp * 16),
                 pB + (size_t)(n0 + row) * Kb + k0 + grp * 8);
        }
    };
    auto issueA = [&](int ch, int stg) {
        const int k0 = ch * BK;
        const __half* pA; int Kd, koff;
        if (AM == 0) { pA = g_xf; Kd = IN_CH; koff = k0; }
        else {
            if (k0 < IN_CH) { pA = g_xf;  Kd = IN_CH; koff = k0; }
            else            { pA = g_x1f; Kd = G_CH;  koff = k0 - IN_CH; }
        }
        const uint32_t sb = base + stg * STAGE;
#pragma unroll
        for (int it = 0; it < IT; it++) {
            int o = tid + it * 256;
            int row = o / GRP, grp = o % GRP;
            cp16(sb + (uint32_t)(row * (RS * 2) + grp * 16),
                 pA + (size_t)(m0 + row) * Kd + koff + grp * 8);
        }
    };
    // fused fp32 A path (BK==32 only)
    float4 ra[2][2];
    auto loadA = [&](int ch) {
        const int k0 = ch * BK;
#pragma unroll
        for (int it = 0; it < 2; it++) {
            int o = tid + it * 256;
            int row = o / GRP, grp = o % GRP;
            int gm = m0 + row;
            if (gm < M) {
                const float4* p = reinterpret_cast<const float4*>(
                    Afp32 + (size_t)gm * K + k0 + grp * 8);
                ra[it][0] = p[0];
                ra[it][1] = p[1];
            } else {
                ra[it][0] = make_float4(0.f, 0.f, 0.f, 0.f);
                ra[it][1] = make_float4(0.f, 0.f, 0.f, 0.f);
            }
        }
    };
    auto storeA = [&](int ch, int stg) {
        const int k0 = ch * BK;
        const uint32_t sb = base + stg * STAGE;
#pragma unroll
        for (int it = 0; it < 2; it++) {
            int o = tid + it * 256;
            int row = o / GRP, grp = o % GRP;
            uint32_t h0 = pack2(ra[it][0].x, ra[it][0].y);
            uint32_t h1 = pack2(ra[it][0].z, ra[it][0].w);
            uint32_t h2 = pack2(ra[it][1].x, ra[it][1].y);
            uint32_t h3 = pack2(ra[it][1].z, ra[it][1].w);
            sts16(sb + (uint32_t)(row * (RS * 2) + grp * 16), h0, h1, h2, h3);
            if (MIRROR) {
                uint4* dst = reinterpret_cast<uint4*>(
                    g_xf + (size_t)(m0 + row) * IN_CH + k0 + grp * 8);
                *dst = make_uint4(h0, h1, h2, h3);
            }
        }
    };
    auto compute = [&](int stg) {
        const uint32_t uA = base + stg * STAGE;
        const uint32_t uB = uA + PLANE;
#pragma unroll
        for (int s = 0; s < BK / 16; s++) {
            const int ks = s * 16 + lko;
            uint32_t bt[4][2];
#pragma unroll
            for (int g = 0; g < 2; g++) {
                uint32_t r[4];
                uint32_t addr = uB + ((wn * 32 + g * 16 + lrow) * RS + ks) * 2;
                ldm_x4(r, addr);
                bt[2 * g][0] = r[0]; bt[2 * g][1] = r[2];
                bt[2 * g + 1][0] = r[1]; bt[2 * g + 1][1] = r[3];
            }
            uint32_t at[4][4];
#pragma unroll
            for (int mt = 0; mt < 4; mt++) {
                uint32_t addr = uA + ((wm * 64 + mt * 16 + lrow) * RS + ks) * 2;
                ldm_x4(at[mt], addr);
            }
#pragma unroll
            for (int mt = 0; mt < 4; mt++)
#pragma unroll
                for (int nt = 0; nt < 4; nt++)
                    mma16816(acc[mt][nt], at[mt], bt[nt]);
        }
    };

    if (AFUSE) {
        loadA(0);
        issueB(0, 0);
        asm volatile("cp.async.commit_group;");
        storeA(0, 0);
        asm volatile("cp.async.wait_group 0;");
        __syncthreads();
        for (int ch = 0; ch < nchunks; ch++) {
            const int stg = ch & 1;
            if (ch + 1 < nchunks) { loadA(ch + 1); issueB(ch + 1, stg ^ 1);
                                    asm volatile("cp.async.commit_group;"); }
            compute(stg);
            if (ch + 1 < nchunks) {
                storeA(ch + 1, stg ^ 1);
                asm volatile("cp.async.wait_group 0;");
            }
            __syncthreads();
        }
    } else if (NST == 2) {
        issueA(0, 0); issueB(0, 0);
        asm volatile("cp.async.commit_group;");
        for (int ch = 0; ch < nchunks; ch++) {
            const int stg = ch & 1;
            if (ch + 1 < nchunks) {
                issueA(ch + 1, stg ^ 1); issueB(ch + 1, stg ^ 1);
                asm volatile("cp.async.commit_group;");
                asm volatile("cp.async.wait_group 1;");
            } else {
                asm volatile("cp.async.wait_group 0;");
            }
            __syncthreads();
            compute(stg);
            __syncthreads();
        }
    } else {   // NST == 3
        issueA(0, 0); issueB(0, 0);
        asm volatile("cp.async.commit_group;");
        if (nchunks > 1) {
            issueA(1, 1); issueB(1, 1);
            asm volatile("cp.async.commit_group;");
        }
        for (int ch = 0; ch < nchunks; ch++) {
            const int stg = ch % 3;
            if (ch + 2 < nchunks) {
                // stage (ch+2)%3 was chunk ch-1's buffer; its compute finished at
                // the end-of-iteration barrier of iteration ch-1.
                issueA(ch + 2, (ch + 2) % 3); issueB(ch + 2, (ch + 2) % 3);
                asm volatile("cp.async.commit_group;");
                asm volatile("cp.async.wait_group 2;");
            } else if (ch + 1 < nchunks) {
                asm volatile("cp.async.wait_group 1;");
            } else {
                asm volatile("cp.async.wait_group 0;");
            }
            __syncthreads();
            compute(stg);
            __syncthreads();
        }
    }

    // ---- epilogue ----
    const int qr = lane >> 2;
    const int qc = (lane & 3) * 2;
#pragma unroll
    for (int mt = 0; mt < 4; mt++) {
#pragma unroll
        for (int nt = 0; nt < 4; nt++) {
#pragma unroll
            for (int half = 0; half < 2; half++) {
                int gm = m0 + wm * 64 + mt * 16 + qr + half * 8;
                if (gm >= M) continue;
                int gn0 = n0 + wn * 32 + nt * 8 + qc;
                float v0 = acc[mt][nt][half * 2 + 0];
                float v1 = acc[mt][nt][half * 2 + 1];
                if (BIAS) { v0 += __ldg(&bias[gn0]); v1 += __ldg(&bias[gn0 + 1]); }
                if (RELU) { v0 = fmaxf(v0, 0.0f); v1 = fmaxf(v1, 0.0f); }
                if (CM == 1) {
                    *reinterpret_cast<__half2*>(&g_xwf[(size_t)gm * G_CH + gn0]) =
                        __floats2half2_rn(v0, v1);
                } else if (HOUT) {
                    *reinterpret_cast<float2*>(&Cp[(size_t)gm * Nout + gn0]) =
                        make_float2(v0, v1);
                } else {
                    if (gn0 < Nout)     Cp[(size_t)gm * Nout + gn0]     = v0;
                    if (gn0 + 1 < Nout) Cp[(size_t)gm * Nout + gn0 + 1] = v1;
                }
            }
        }
    }
}

// ---------------- edge dtype probe ----------------
__global__ void k_detect(const void* ei_raw, int E, int n) {
    if (threadIdx.x == 0 && blockIdx.x == 0) {
        const long long* p = (const long long*)ei_raw;
        int bad = 0;
        int samples = E < 512 ? E : 512;
        for (int i = 0; i < samples; i++) {
            long long v = p[i];
            if (v < 0 || v >= n) { bad = 1; break; }
        }
        g_i64mode = bad ? 0 : 1;
    }
}
__device__ __forceinline__ int edge_at(const void* ei_raw, size_t idx) {
    if (g_i64mode) return (int)((const long long*)ei_raw)[idx];
    return ((const int*)ei_raw)[idx];
}

// ---------------- CSR build ----------------
__global__ void k_count(const void* __restrict__ ei, int E, int n) {
    int i = blockIdx.x * blockDim.x + threadIdx.x;
    if (i < E) {
        int t = edge_at(ei, (size_t)E + i);
        t = max(0, min(n - 1, t));
        atomicAdd(&g_cnt[t], 1);
    }
}
// scan + dinv fused: exclusive block scan of g_cnt, dinv = rsqrt(cnt+1)
__global__ void k_scan1(int n) {
    __shared__ int s[SCAN_B];
    int i = blockIdx.x * SCAN_B + threadIdx.x;
    int v = (i < n) ? g_cnt[i] : 0;
    if (i < n) g_dinv[i] = rsqrtf((float)(v + 1));
    s[threadIdx.x] = v;
    __syncthreads();
#pragma unroll
    for (int d = 1; d < SCAN_B; d <<= 1) {
        int t = (threadIdx.x >= d) ? s[threadIdx.x - d] : 0;
        __syncthreads();
        s[threadIdx.x] += t;
        __syncthreads();
    }
    if (i < n) g_offs[i] = s[threadIdx.x] - v;
    if (threadIdx.x == SCAN_B - 1) g_bsum[blockIdx.x] = s[threadIdx.x];
}
__global__ void k_scan2(int nb) {
    __shared__ int s[256];
    int v = (threadIdx.x < nb) ? g_bsum[threadIdx.x] : 0;
    s[threadIdx.x] = v;
    __syncthreads();
#pragma unroll
    for (int d = 1; d < 256; d <<= 1) {
        int t = (threadIdx.x >= d) ? s[threadIdx.x - d] : 0;
        __syncthreads();
        s[threadIdx.x] += t;
        __syncthreads();
    }
    if (threadIdx.x < nb) g_bsum[threadIdx.x] = s[threadIdx.x] - v;
}
__global__ void k_scan3(int n, int E) {
    int i = blockIdx.x * blockDim.x + threadIdx.x;
    if (i < n) {
        int o = g_offs[i] + g_bsum[i / SCAN_B];
        g_offs[i] = o;
        g_cur[i]  = o;
    }
    if (i == 0) g_offs[n] = E;
}
__global__ void k_fill(const void* __restrict__ ei, int E, int n) {
    int e = blockIdx.x * blockDim.x + threadIdx.x;
    if (e >= E) return;
    int r = edge_at(ei, e);
    int c = edge_at(ei, (size_t)E + e);
    r = max(0, min(n - 1, r));
    c = max(0, min(n - 1, c));
    int pos = atomicAdd(&g_cur[c], 1);
    g_esrc[pos] = r;
}

// ---------------- warp-per-node gather ----------------
__global__ void k_gather(const float* __restrict__ b, int n) {
    int node = (blockIdx.x * blockDim.x + threadIdx.x) >> 5;
    int lane = threadIdx.x & 31;
    if (node >= n) return;
    const float dc = g_dinv[node];
    const int beg = g_offs[node], end = g_offs[node + 1];

    const __half2* selfrow = reinterpret_cast<const __half2*>(g_xwf + (size_t)node * G_CH);
    float2 s0 = __half22float2(selfrow[lane]);
    float2 s1 = __half22float2(selfrow[lane + 32]);
    float ws = dc * dc;
    float a0 = s0.x * ws, a1 = s0.y * ws, a2 = s1.x * ws, a3 = s1.y * ws;

    for (int e = beg; e < end; e++) {
        int r = g_esrc[e];
        float w = g_dinv[r] * dc;
        const __half2* src = reinterpret_cast<const __half2*>(g_xwf + (size_t)r * G_CH);
        float2 f0 = __half22float2(src[lane]);
        float2 f1 = __half22float2(src[lane + 32]);
        a0 = fmaf(f0.x, w, a0); a1 = fmaf(f0.y, w, a1);
        a2 = fmaf(f1.x, w, a2); a3 = fmaf(f1.y, w, a3);
    }
    int c0 = 2 * lane, c1 = 2 * (lane + 32);
    a0 = fmaxf(a0 + __ldg(&b[c0]),     0.0f);
    a1 = fmaxf(a1 + __ldg(&b[c0 + 1]), 0.0f);
    a2 = fmaxf(a2 + __ldg(&b[c1]),     0.0f);
    a3 = fmaxf(a3 + __ldg(&b[c1 + 1]), 0.0f);
    __half2* dst = reinterpret_cast<__half2*>(g_x1f + (size_t)node * G_CH);
    dst[lane]      = __floats2half2_rn(a0, a1);
    dst[lane + 32] = __floats2half2_rn(a2, a3);
}

// ---------------- launch ----------------
#define SMEM_32_2 (2 * 2 * 128 * (32 + 8) * 2)   // 40960
#define SMEM_64_3 (3 * 2 * 128 * (64 + 8) * 2)   // 110592

extern "C" void kernel_launch(void* const* d_in, const int* in_sizes, int n_in,
                              void* d_out, int out_size) {
    const float* x     = nullptr;  int x_cnt = 0;
    const void*  ei    = nullptr;  int ei_cnt = 0;
    const float* W_gcn = nullptr;
    const float* b_gcn = nullptr;
    const float* W_hid = nullptr;
    const float* b_hid = nullptr;
    const float* W_cls = nullptr;
    const float* b_cls = nullptr;

    int max_cnt = 0;
    for (int i = 0; i < n_in; i++) if (in_sizes[i] > max_cnt) max_cnt = in_sizes[i];
    for (int i = 0; i < n_in; i++) {
        int c = in_sizes[i];
        if      (c == IN_CH * G_CH)  W_gcn = (const float*)d_in[i];
        else if (c == KCAT * HID)    W_hid = (const float*)d_in[i];
        else if (c == HID * NCLS)    W_cls = (const float*)d_in[i];
        else if (c == G_CH)          b_gcn = (const float*)d_in[i];
        else if (c == HID)           b_hid = (const float*)d_in[i];
        else if (c == NCLS)          b_cls = (const float*)d_in[i];
        else if (c == max_cnt && c % IN_CH == 0) { x = (const float*)d_in[i]; x_cnt = c; }
    }
    const int N = x_cnt / IN_CH;

    for (int i = 0; i < n_in; i++) {
        const void* p = d_in[i];
        if (p == (const void*)x || p == (const void*)W_gcn || p == (const void*)W_hid ||
            p == (const void*)W_cls || p == (const void*)b_gcn || p == (const void*)b_hid ||
            p == (const void*)b_cls) continue;
        int c = in_sizes[i];
        if (c != 2 * N) { ei = p; ei_cnt = c; }
        else if (ei == nullptr) { ei = p; ei_cnt = c; }
    }
    const int E = ei_cnt / 2;

    float* h      = (float*)d_out;
    float* logits = h + (size_t)N * HID;

    const int mblocks = (N + 127) / 128;
    const int nscan   = (N + SCAN_B - 1) / SCAN_B;

    // raise dynamic smem cap for the 3-stage BK=64 GEMM2
    cudaFuncSetAttribute(tc_gemm<false, false, 64, 3, 1, 1, true, true, true, 0>,
                         cudaFuncAttributeMaxDynamicSharedMemorySize, SMEM_64_3);

    // 0) probe + combined prep (weights + cnt zero)
    k_detect<<<1, 32>>>(ei, E, N);
    int prep_tot = WG_TOT + WH_TOT + WC_TOT + N;
    k_prep<<<(prep_tot + 255) / 256, 256>>>(W_gcn, W_hid, W_cls, N);

    // 1) fused: xw = x @ W_gcn -> g_xwf, AND x -> g_xf (fp16)
    tc_gemm<true, true, 32, 2, 0, 0, false, false, false, 1>
        <<<dim3(mblocks, 1), 256, SMEM_32_2>>>(x, nullptr, nullptr, N, G_CH);

    // 2) CSR build (dinv fused into scan1)
    k_count<<<(E + 255) / 256, 256>>>(ei, E, N);
    k_scan1<<<nscan, SCAN_B>>>(N);
    k_scan2<<<1, 256>>>(nscan);
    k_scan3<<<(N + 255) / 256, 256>>>(N, E);
    k_fill<<<(E + 255) / 256, 256>>>(ei, E, N);

    // 3) gather-aggregate -> x1 fp16
    k_gather<<<(N * 32 + 255) / 256, 256>>>(b_gcn, N);

    // 4) h = relu([x | x1] @ W_hid + b_hid) -> d_out; n-fast grid, BK=64, 3-stage
    tc_gemm<false, false, 64, 3, 1, 1, true, true, true, 0>
        <<<dim3(4, mblocks), 256, SMEM_64_3>>>(nullptr, b_hid, h, N, HID);

    // 5) logits = h @ W_cls + b_cls (reads fp32 h from d_out)
    tc_gemm<true, false, 32, 2, 2, 2, true, false, false, 0>
        <<<dim3(mblocks, 1), 256, SMEM_32_2>>>(h, b_cls, logits, N, NCLS);
}

// round 17
// speedup vs baseline: 1.0086x; 1.0086x over previous
#include <cuda_runtime.h>
#include <cuda_fp16.h>
#include <cstdint>

#define N_NODES 100000
#define N_PAD   100096
#define E_MAX   700000
#define IN_CH   1280
#define G_CH    128
#define HID     512
#define NCLS    79
#define KCAT    (IN_CH + G_CH)
#define SCAN_B  512

// ---------------- scratch (device globals; no allocation allowed) ----------------
__device__ float  g_dinv[N_NODES];
__device__ int    g_cnt [N_NODES];
__device__ int    g_offs[N_NODES + 1];
__device__ int    g_cur [N_NODES];
__device__ int    g_bsum[256];
__device__ int    g_esrc[E_MAX];
__device__ int    g_i64mode;
__device__ __half g_xwf[(size_t)N_PAD * G_CH];
__device__ __half g_xf [(size_t)N_PAD * IN_CH];
__device__ __half g_x1f[(size_t)N_PAD * G_CH];
__device__ __half g_wgf[G_CH * IN_CH];
__device__ __half g_whf[HID * KCAT];
__device__ __half g_wcf[128 * HID];

// ---------------- PTX helpers ----------------
__device__ __forceinline__ uint32_t smem_u32(const void* p) {
    uint32_t a;
    asm("{ .reg .u64 t; cvta.to.shared.u64 t, %1; cvt.u32.u64 %0, t; }" : "=r"(a) : "l"(p));
    return a;
}
__device__ __forceinline__ void cp16(uint32_t dst, const void* src) {
    asm volatile("cp.async.cg.shared.global [%0], [%1], 16;" :: "r"(dst), "l"(src));
}
__device__ __forceinline__ void ldm_x4(uint32_t* r, uint32_t addr) {
    asm volatile("ldmatrix.sync.aligned.m8n8.x4.shared.b16 {%0,%1,%2,%3}, [%4];"
        : "=r"(r[0]), "=r"(r[1]), "=r"(r[2]), "=r"(r[3]) : "r"(addr));
}
__device__ __forceinline__ void mma16816(float* c, const uint32_t* a, const uint32_t* b) {
    asm volatile("mma.sync.aligned.m16n8k16.row.col.f32.f16.f16.f32 "
        "{%0,%1,%2,%3}, {%4,%5,%6,%7}, {%8,%9}, {%0,%1,%2,%3};"
        : "+f"(c[0]), "+f"(c[1]), "+f"(c[2]), "+f"(c[3])
        : "r"(a[0]), "r"(a[1]), "r"(a[2]), "r"(a[3]), "r"(b[0]), "r"(b[1]));
}
__device__ __forceinline__ void sts16(uint32_t addr, uint32_t a, uint32_t b, uint32_t c, uint32_t d) {
    asm volatile("st.shared.v4.b32 [%0], {%1,%2,%3,%4};" :: "r"(addr), "r"(a), "r"(b), "r"(c), "r"(d));
}
__device__ __forceinline__ uint32_t pack2(float a, float b) {
    __half2 h = __floats2half2_rn(a, b);
    return *reinterpret_cast<uint32_t*>(&h);
}
// streaming (write-through) 16B store: data written once, read once much later
__device__ __forceinline__ void stg16_cs(void* p, uint4 v) {
    asm volatile("st.global.cs.v4.b32 [%0], {%1,%2,%3,%4};"
        :: "l"(p), "r"(v.x), "r"(v.y), "r"(v.z), "r"(v.w) : "memory");
}

// ---------------- combined prep: convert all weights + zero g_cnt ----------------
#define WG_TOT (G_CH * IN_CH)
#define WH_TOT (HID * KCAT)
#define WC_TOT (128 * HID)
__global__ void k_prep(const float* __restrict__ Wg, const float* __restrict__ Wh,
                       const float* __restrict__ Wc, int n) {
    int idx = blockIdx.x * blockDim.x + threadIdx.x;
    if (idx < WG_TOT) {
        int nn = idx / IN_CH, k = idx % IN_CH;
        g_wgf[idx] = __float2half_rn(__ldg(&Wg[(size_t)k * G_CH + nn]));
        return;
    }
    idx -= WG_TOT;
    if (idx < WH_TOT) {
        int nn = idx / KCAT, k = idx % KCAT;
        g_whf[idx] = __float2half_rn(__ldg(&Wh[(size_t)k * HID + nn]));
        return;
    }
    idx -= WH_TOT;
    if (idx < WC_TOT) {
        int nn = idx / HID, k = idx % HID;
        float v = (nn < NCLS) ? __ldg(&Wc[(size_t)k * NCLS + nn]) : 0.0f;
        g_wcf[idx] = __float2half_rn(v);
        return;
    }
    idx -= WC_TOT;
    if (idx < n) g_cnt[idx] = 0;
}

// ---------------- pipelined fp16 tensor-core GEMM ----------------
// AFUSE: A read as fp32 (stride K), converted in regs; MIRROR: also store fp16 A
//        to g_xf (streaming stores). Otherwise A via 2-stage cp.async pipeline.
template<bool AFUSE, bool MIRROR, int BK, int AM, int BMODE,
         bool BIAS, bool RELU, bool HOUT, int CM>
__global__ void __launch_bounds__(256, 2)
tc_gemm(const float* __restrict__ Afp32, const float* __restrict__ bias,
        float* __restrict__ Cp, int M, int Nout)
{
    constexpr int RS    = BK + 8;
    constexpr int PLANE = 128 * RS * 2;
    constexpr int STAGE = 2 * PLANE;
    constexpr int GRP   = BK / 8;
    constexpr int IT    = BK / 16;

    extern __shared__ __align__(16) char dsm[];
    const uint32_t base = smem_u32(dsm);

    const int tid  = threadIdx.x;
    const int wid  = tid >> 5;
    const int lane = tid & 31;
    const int wm = wid >> 2;
    const int wn = wid & 3;
    const int m0 = (HOUT ? blockIdx.y : blockIdx.x) * 128;
    const int n0 = (HOUT ? blockIdx.x : blockIdx.y) * 128;

    float acc[4][4][4];
#pragma unroll
    for (int i = 0; i < 4; i++)
#pragma unroll
        for (int j = 0; j < 4; j++)
#pragma unroll
            for (int r = 0; r < 4; r++) acc[i][j][r] = 0.0f;

    constexpr int K  = (AM == 0) ? IN_CH : (AM == 1) ? KCAT : HID;
    constexpr int Kb = (BMODE == 0) ? IN_CH : (BMODE == 1) ? KCAT : HID;
    constexpr int nchunks = K / BK;

    const int lrow = lane & 15;
    const int lko  = (lane >> 4) << 3;

    auto issueB = [&](int ch, int stg) {
        const int k0 = ch * BK;
        const __half* pB = (BMODE == 0) ? g_wgf : (BMODE == 1) ? g_whf : g_wcf;
        const uint32_t sb = base + stg * STAGE + PLANE;
#pragma unroll
        for (int it = 0; it < IT; it++) {
            int o = tid + it * 256;
            int row = o / GRP, grp = o % GRP;
            cp16(sb + (uint32_t)(row * (RS * 2) + grp * 16),
                 pB + (size_t)(n0 + row) * Kb + k0 + grp * 8);
        }
    };
    auto issueA = [&](int ch, int stg) {
        const int k0 = ch * BK;
        const __half* pA; int Kd, koff;
        if (AM == 0) { pA = g_xf; Kd = IN_CH; koff = k0; }
        else {
            if (k0 < IN_CH) { pA = g_xf;  Kd = IN_CH; koff = k0; }
            else            { pA = g_x1f; Kd = G_CH;  koff = k0 - IN_CH; }
        }
        const uint32_t sb = base + stg * STAGE;
#pragma unroll
        for (int it = 0; it < IT; it++) {
            int o = tid + it * 256;
            int row = o / GRP, grp = o % GRP;
            cp16(sb + (uint32_t)(row * (RS * 2) + grp * 16),
                 pA + (size_t)(m0 + row) * Kd + koff + grp * 8);
        }
    };
    // fused fp32 A path (BK==32 only)
    float4 ra[2][2];
    auto loadA = [&](int ch) {
        const int k0 = ch * BK;
#pragma unroll
        for (int it = 0; it < 2; it++) {
            int o = tid + it * 256;
            int row = o / GRP, grp = o % GRP;
            int gm = m0 + row;
            if (gm < M) {
                const float4* p = reinterpret_cast<const float4*>(
                    Afp32 + (size_t)gm * K + k0 + grp * 8);
                ra[it][0] = p[0];
                ra[it][1] = p[1];
            } else {
                ra[it][0] = make_float4(0.f, 0.f, 0.f, 0.f);
                ra[it][1] = make_float4(0.f, 0.f, 0.f, 0.f);
            }
        }
    };
    auto storeA = [&](int ch, int stg) {
        const int k0 = ch * BK;
        const uint32_t sb = base + stg * STAGE;
#pragma unroll
        for (int it = 0; it < 2; it++) {
            int o = tid + it * 256;
            int row = o / GRP, grp = o % GRP;
            uint32_t h0 = pack2(ra[it][0].x, ra[it][0].y);
            uint32_t h1 = pack2(ra[it][0].z, ra[it][0].w);
            uint32_t h2 = pack2(ra[it][1].x, ra[it][1].y);
            uint32_t h3 = pack2(ra[it][1].z, ra[it][1].w);
            sts16(sb + (uint32_t)(row * (RS * 2) + grp * 16), h0, h1, h2, h3);
            if (MIRROR) {
                stg16_cs(g_xf + (size_t)(m0 + row) * IN_CH + k0 + grp * 8,
                         make_uint4(h0, h1, h2, h3));
            }
        }
    };
    auto compute = [&](int stg) {
        const uint32_t uA = base + stg * STAGE;
        const uint32_t uB = uA + PLANE;
#pragma unroll
        for (int s = 0; s < BK / 16; s++) {
            const int ks = s * 16 + lko;
            uint32_t bt[4][2];
#pragma unroll
            for (int g = 0; g < 2; g++) {
                uint32_t r[4];
                uint32_t addr = uB + ((wn * 32 + g * 16 + lrow) * RS + ks) * 2;
                ldm_x4(r, addr);
                bt[2 * g][0] = r[0]; bt[2 * g][1] = r[2];
                bt[2 * g + 1][0] = r[1]; bt[2 * g + 1][1] = r[3];
            }
            uint32_t at[4][4];
#pragma unroll
            for (int mt = 0; mt < 4; mt++) {
                uint32_t addr = uA + ((wm * 64 + mt * 16 + lrow) * RS + ks) * 2;
                ldm_x4(at[mt], addr);
            }
#pragma unroll
            for (int mt = 0; mt < 4; mt++)
#pragma unroll
                for (int nt = 0; nt < 4; nt++)
                    mma16816(acc[mt][nt], at[mt], bt[nt]);
        }
    };

    if (AFUSE) {
        loadA(0);
        issueB(0, 0);
        asm volatile("cp.async.commit_group;");
        storeA(0, 0);
        asm volatile("cp.async.wait_group 0;");
        __syncthreads();
        for (int ch = 0; ch < nchunks; ch++) {
            const int stg = ch & 1;
            if (ch + 1 < nchunks) { loadA(ch + 1); issueB(ch + 1, stg ^ 1);
                                    asm volatile("cp.async.commit_group;"); }
            compute(stg);
            if (ch + 1 < nchunks) {
                storeA(ch + 1, stg ^ 1);
                asm volatile("cp.async.wait_group 0;");
            }
            __syncthreads();
        }
    } else {
        issueA(0, 0); issueB(0, 0);
        asm volatile("cp.async.commit_group;");
        for (int ch = 0; ch < nchunks; ch++) {
            const int stg = ch & 1;
            if (ch + 1 < nchunks) {
                issueA(ch + 1, stg ^ 1); issueB(ch + 1, stg ^ 1);
                asm volatile("cp.async.commit_group;");
                asm volatile("cp.async.wait_group 1;");
            } else {
                asm volatile("cp.async.wait_group 0;");
            }
            __syncthreads();
            compute(stg);
            __syncthreads();
        }
    }

    // ---- epilogue ----
    const int qr = lane >> 2;
    const int qc = (lane & 3) * 2;
#pragma unroll
    for (int mt = 0; mt < 4; mt++) {
#pragma unroll
        for (int nt = 0; nt < 4; nt++) {
#pragma unroll
            for (int half = 0; half < 2; half++) {
                int gm = m0 + wm * 64 + mt * 16 + qr + half * 8;
                if (gm >= M) continue;
                int gn0 = n0 + wn * 32 + nt * 8 + qc;
                float v0 = acc[mt][nt][half * 2 + 0];
                float v1 = acc[mt][nt][half * 2 + 1];
                if (BIAS) { v0 += __ldg(&bias[gn0]); v1 += __ldg(&bias[gn0 + 1]); }
                if (RELU) { v0 = fmaxf(v0, 0.0f); v1 = fmaxf(v1, 0.0f); }
                if (CM == 1) {
                    *reinterpret_cast<__half2*>(&g_xwf[(size_t)gm * G_CH + gn0]) =
                        __floats2half2_rn(v0, v1);
                } else if (HOUT) {
                    *reinterpret_cast<float2*>(&Cp[(size_t)gm * Nout + gn0]) =
                        make_float2(v0, v1);
                } else {
                    if (gn0 < Nout)     Cp[(size_t)gm * Nout + gn0]     = v0;
                    if (gn0 + 1 < Nout) Cp[(size_t)gm * Nout + gn0 + 1] = v1;
                }
            }
        }
    }
}

// ---------------- edge dtype probe ----------------
__global__ void k_detect(const void* ei_raw, int E, int n) {
    if (threadIdx.x == 0 && blockIdx.x == 0) {
        const long long* p = (const long long*)ei_raw;
        int bad = 0;
        int samples = E < 512 ? E : 512;
        for (int i = 0; i < samples; i++) {
            long long v = p[i];
            if (v < 0 || v >= n) { bad = 1; break; }
        }
        g_i64mode = bad ? 0 : 1;
    }
}
__device__ __forceinline__ int edge_at(const void* ei_raw, size_t idx) {
    if (g_i64mode) return (int)((const long long*)ei_raw)[idx];
    return ((const int*)ei_raw)[idx];
}

// ---------------- CSR build ----------------
__global__ void k_count(const void* __restrict__ ei, int E, int n) {
    int i = blockIdx.x * blockDim.x + threadIdx.x;
    if (i < E) {
        int t = edge_at(ei, (size_t)E + i);
        t = max(0, min(n - 1, t));
        atomicAdd(&g_cnt[t], 1);
    }
}
__global__ void k_scan1(int n) {
    __shared__ int s[SCAN_B];
    int i = blockIdx.x * SCAN_B + threadIdx.x;
    int v = (i < n) ? g_cnt[i] : 0;
    if (i < n) g_dinv[i] = rsqrtf((float)(v + 1));
    s[threadIdx.x] = v;
    __syncthreads();
#pragma unroll
    for (int d = 1; d < SCAN_B; d <<= 1) {
        int t = (threadIdx.x >= d) ? s[threadIdx.x - d] : 0;
        __syncthreads();
        s[threadIdx.x] += t;
        __syncthreads();
    }
    if (i < n) g_offs[i] = s[threadIdx.x] - v;
    if (threadIdx.x == SCAN_B - 1) g_bsum[blockIdx.x] = s[threadIdx.x];
}
__global__ void k_scan2(int nb) {
    __shared__ int s[256];
    int v = (threadIdx.x < nb) ? g_bsum[threadIdx.x] : 0;
    s[threadIdx.x] = v;
    __syncthreads();
#pragma unroll
    for (int d = 1; d < 256; d <<= 1) {
        int t = (threadIdx.x >= d) ? s[threadIdx.x - d] : 0;
        __syncthreads();
        s[threadIdx.x] += t;
        __syncthreads();
    }
    if (threadIdx.x < nb) g_bsum[threadIdx.x] = s[threadIdx.x] - v;
}
__global__ void k_scan3(int n, int E) {
    int i = blockIdx.x * blockDim.x + threadIdx.x;
    if (i < n) {
        int o = g_offs[i] + g_bsum[i / SCAN_B];
        g_offs[i] = o;
        g_cur[i]  = o;
    }
    if (i == 0) g_offs[n] = E;
}
__global__ void k_fill(const void* __restrict__ ei, int E, int n) {
    int e = blockIdx.x * blockDim.x + threadIdx.x;
    if (e >= E) return;
    int r = edge_at(ei, e);
    int c = edge_at(ei, (size_t)E + e);
    r = max(0, min(n - 1, r));
    c = max(0, min(n - 1, c));
    int pos = atomicAdd(&g_cur[c], 1);
    g_esrc[pos] = r;
}

// ---------------- warp-per-node gather ----------------
__global__ void k_gather(const float* __restrict__ b, int n) {
    int node = (blockIdx.x * blockDim.x + threadIdx.x) >> 5;
    int lane = threadIdx.x & 31;
    if (node >= n) return;
    const float dc = g_dinv[node];
    const int beg = g_offs[node], end = g_offs[node + 1];

    const __half2* selfrow = reinterpret_cast<const __half2*>(g_xwf + (size_t)node * G_CH);
    float2 s0 = __half22float2(selfrow[lane]);
    float2 s1 = __half22float2(selfrow[lane + 32]);
    float ws = dc * dc;
    float a0 = s0.x * ws, a1 = s0.y * ws, a2 = s1.x * ws, a3 = s1.y * ws;

    for (int e = beg; e < end; e++) {
        int r = g_esrc[e];
        float w = g_dinv[r] * dc;
        const __half2* src = reinterpret_cast<const __half2*>(g_xwf + (size_t)r * G_CH);
        float2 f0 = __half22float2(src[lane]);
        float2 f1 = __half22float2(src[lane + 32]);
        a0 = fmaf(f0.x, w, a0); a1 = fmaf(f0.y, w, a1);
        a2 = fmaf(f1.x, w, a2); a3 = fmaf(f1.y, w, a3);
    }
    int c0 = 2 * lane, c1 = 2 * (lane + 32);
    a0 = fmaxf(a0 + __ldg(&b[c0]),     0.0f);
    a1 = fmaxf(a1 + __ldg(&b[c0 + 1]), 0.0f);
    a2 = fmaxf(a2 + __ldg(&b[c1]),     0.0f);
    a3 = fmaxf(a3 + __ldg(&b[c1 + 1]), 0.0f);
    __half2* dst = reinterpret_cast<__half2*>(g_x1f + (size_t)node * G_CH);
    dst[lane]      = __floats2half2_rn(a0, a1);
    dst[lane + 32] = __floats2half2_rn(a2, a3);
}

// ---------------- launch ----------------
#define SMEM_32_2 (2 * 2 * 128 * (32 + 8) * 2)   // 40960
#define SMEM_64_2 (2 * 2 * 128 * (64 + 8) * 2)   // 73728

extern "C" void kernel_launch(void* const* d_in, const int* in_sizes, int n_in,
                              void* d_out, int out_size) {
    const float* x     = nullptr;  int x_cnt = 0;
    const void*  ei    = nullptr;  int ei_cnt = 0;
    const float* W_gcn = nullptr;
    const float* b_gcn = nullptr;
    const float* W_hid = nullptr;
    const float* b_hid = nullptr;
    const float* W_cls = nullptr;
    const float* b_cls = nullptr;

    int max_cnt = 0;
    for (int i = 0; i < n_in; i++) if (in_sizes[i] > max_cnt) max_cnt = in_sizes[i];
    for (int i = 0; i < n_in; i++) {
        int c = in_sizes[i];
        if      (c == IN_CH * G_CH)  W_gcn = (const float*)d_in[i];
        else if (c == KCAT * HID)    W_hid = (const float*)d_in[i];
        else if (c == HID * NCLS)    W_cls = (const float*)d_in[i];
        else if (c == G_CH)          b_gcn = (const float*)d_in[i];
        else if (c == HID)           b_hid = (const float*)d_in[i];
        else if (c == NCLS)          b_cls = (const float*)d_in[i];
        else if (c == max_cnt && c % IN_CH == 0) { x = (const float*)d_in[i]; x_cnt = c; }
    }
    const int N = x_cnt / IN_CH;

    for (int i = 0; i < n_in; i++) {
        const void* p = d_in[i];
        if (p == (const void*)x || p == (const void*)W_gcn || p == (const void*)W_hid ||
            p == (const void*)W_cls || p == (const void*)b_gcn || p == (const void*)b_hid ||
            p == (const void*)b_cls) continue;
        int c = in_sizes[i];
        if (c != 2 * N) { ei = p; ei_cnt = c; }
        else if (ei == nullptr) { ei = p; ei_cnt = c; }
    }
    const int E = ei_cnt / 2;

    float* h      = (float*)d_out;
    float* logits = h + (size_t)N * HID;

    const int mblocks = (N + 127) / 128;
    const int nscan   = (N + SCAN_B - 1) / SCAN_B;

    cudaFuncSetAttribute(tc_gemm<false, false, 64, 1, 1, true, true, true, 0>,
                         cudaFuncAttributeMaxDynamicSharedMemorySize, SMEM_64_2);

    // 0) probe + combined prep (weights + cnt zero)
    k_detect<<<1, 32>>>(ei, E, N);
    int prep_tot = WG_TOT + WH_TOT + WC_TOT + N;
    k_prep<<<(prep_tot + 255) / 256, 256>>>(W_gcn, W_hid, W_cls, N);

    // 1) fused: xw = x @ W_gcn -> g_xwf, AND x -> g_xf (fp16, streaming stores)
    tc_gemm<true, true, 32, 0, 0, false, false, false, 1>
        <<<dim3(mblocks, 1), 256, SMEM_32_2>>>(x, nullptr, nullptr, N, G_CH);

    // 2) CSR build (dinv fused into scan1)
    k_count<<<(E + 255) / 256, 256>>>(ei, E, N);
    k_scan1<<<nscan, SCAN_B>>>(N);
    k_scan2<<<1, 256>>>(nscan);
    k_scan3<<<(N + 255) / 256, 256>>>(N, E);
    k_fill<<<(E + 255) / 256, 256>>>(ei, E, N);

    // 3) gather-aggregate -> x1 fp16
    k_gather<<<(N * 32 + 255) / 256, 256>>>(b_gcn, N);

    // 4) h = relu([x | x1] @ W_hid + b_hid) -> d_out; n-fast grid, BK=64, 2-stage
    tc_gemm<false, false, 64, 1, 1, true, true, true, 0>
        <<<dim3(4, mblocks), 256, SMEM_64_2>>>(nullptr, b_hid, h, N, HID);

    // 5) logits = h @ W_cls + b_cls (reads fp32 h from d_out)
    tc_gemm<true, false, 32, 2, 2, true, false, false, 0>
        <<<dim3(mblocks, 1), 256, SMEM_32_2>>>(h, b_cls, logits, N, NCLS);
}